// round 4
// baseline (speedup 1.0000x reference)
#include <cuda_runtime.h>

// PatchEmbedding as implicit-im2col fp32 SGEMM.
// A[m,k] = x[n, c, gi*14+r, gj*12+q]  (m -> (n, valid patch), k = c*168 + r*12 + q)
// B[k,e] = W[e, c, r, q]  (W is [E, K] row-major with the same k ordering)
// out[m,e] = sum_k A*B + bias[e],  out is [B*T*N_VALID, E] row-major == d_out.

namespace {

constexpr int NIMG = 96;          // B*T
constexpr int C    = 4;
constexpr int H    = 420;
constexpr int W    = 312;
constexpr int PH   = 14;
constexpr int PW   = 12;
constexpr int GW   = 26;          // W / PW
constexpr int E    = 768;
constexpr int NV   = 390;
constexpr int K    = 672;         // C*PH*PW
constexpr int M    = NIMG * NV;   // 37440
constexpr int HW_  = H * W;       // 131040
constexpr int CHW  = C * HW_;     // 524160

constexpr int BM = 128;
constexpr int BN = 128;
constexpr int BK = 8;
constexpr int NKT = K / BK;       // 84

__global__ __launch_bounds__(256, 2)
void patch_embed_gemm(const float* __restrict__ x,
                      const float* __restrict__ Wm,
                      const float* __restrict__ bias,
                      const int*   __restrict__ valid,
                      float*       __restrict__ out)
{
    __shared__ float As[BK][BM];
    __shared__ float Bs[BK][BN];
    __shared__ int   koff[K];
    __shared__ int   rowbase_s[BM];

    const int tid = threadIdx.x;
    const int m0  = blockIdx.x * BM;
    const int n0  = blockIdx.y * BN;

    // k -> offset within an image relative to the patch base pointer
    for (int k = tid; k < K; k += 256) {
        int c   = k / (PH * PW);
        int rem = k - c * (PH * PW);
        int r   = rem / PW;
        int q   = rem - r * PW;
        koff[k] = c * HW_ + r * W + q;
    }
    // m -> base offset of that row's patch (image + patch origin)
    if (tid < BM) {
        int mg   = m0 + tid;
        int base = -1;
        if (mg < M) {
            int n  = mg / NV;
            int v  = mg - n * NV;
            int p  = valid[v];
            int gi = p / GW;
            int gj = p - gi * GW;
            base = n * CHW + gi * (PH * W) + gj * PW;
        }
        rowbase_s[tid] = base;
    }
    __syncthreads();

    // ---- global-load assignment: thread -> (row lm, 4 consecutive k at lkq)
    const int  lm  = tid >> 1;           // 0..127
    const int  lkq = (tid & 1) << 2;     // 0 or 4
    const int  rb  = rowbase_s[lm];
    const bool av  = (rb >= 0);
    const float4* wrow =
        reinterpret_cast<const float4*>(Wm + (size_t)(n0 + lm) * K);

    // ---- compute assignment: 8x8 micro-tile split 4+4 (conflict-free LDS.128)
    const int row0 = (tid >> 4) << 2;    // ty*4, rows row0..+3 and row0+64..+67
    const int col0 = (tid & 15) << 2;    // tx*4, cols col0..+3 and col0+64..+67

    float acc[8][8];
    #pragma unroll
    for (int i = 0; i < 8; ++i)
        #pragma unroll
        for (int j = 0; j < 8; ++j)
            acc[i][j] = 0.0f;

    // prologue: stage tile 0 into registers
    float  ar[4];
    float4 br;
    {
        #pragma unroll
        for (int j = 0; j < 4; ++j)
            ar[j] = av ? __ldg(&x[rb + koff[lkq + j]]) : 0.0f;
        br = wrow[lkq >> 2];
    }

    for (int kt = 0; kt < NKT; ++kt) {
        // staged regs -> smem
        #pragma unroll
        for (int j = 0; j < 4; ++j) As[lkq + j][lm] = ar[j];
        Bs[lkq + 0][lm] = br.x;
        Bs[lkq + 1][lm] = br.y;
        Bs[lkq + 2][lm] = br.z;
        Bs[lkq + 3][lm] = br.w;
        __syncthreads();

        // prefetch next k-slab while computing this one
        if (kt + 1 < NKT) {
            int kb = (kt + 1) * BK + lkq;
            #pragma unroll
            for (int j = 0; j < 4; ++j)
                ar[j] = av ? __ldg(&x[rb + koff[kb + j]]) : 0.0f;
            br = wrow[kb >> 2];
        }

        #pragma unroll
        for (int kk = 0; kk < BK; ++kk) {
            float4 a0 = *reinterpret_cast<const float4*>(&As[kk][row0]);
            float4 a1 = *reinterpret_cast<const float4*>(&As[kk][row0 + 64]);
            float4 b0 = *reinterpret_cast<const float4*>(&Bs[kk][col0]);
            float4 b1 = *reinterpret_cast<const float4*>(&Bs[kk][col0 + 64]);
            float a[8] = {a0.x, a0.y, a0.z, a0.w, a1.x, a1.y, a1.z, a1.w};
            float b[8] = {b0.x, b0.y, b0.z, b0.w, b1.x, b1.y, b1.z, b1.w};
            #pragma unroll
            for (int i = 0; i < 8; ++i)
                #pragma unroll
                for (int j = 0; j < 8; ++j)
                    acc[i][j] = fmaf(a[i], b[j], acc[i][j]);
        }
        __syncthreads();
    }

    // epilogue: + bias, float4 stores
    float4 bv0 = *reinterpret_cast<const float4*>(bias + n0 + col0);
    float4 bv1 = *reinterpret_cast<const float4*>(bias + n0 + col0 + 64);

    #pragma unroll
    for (int ih = 0; ih < 2; ++ih) {
        #pragma unroll
        for (int i = 0; i < 4; ++i) {
            int mg = m0 + ih * 64 + row0 + i;
            if (mg < M) {
                int ai = ih * 4 + i;
                float4 o0 = make_float4(acc[ai][0] + bv0.x, acc[ai][1] + bv0.y,
                                        acc[ai][2] + bv0.z, acc[ai][3] + bv0.w);
                float4 o1 = make_float4(acc[ai][4] + bv1.x, acc[ai][5] + bv1.y,
                                        acc[ai][6] + bv1.z, acc[ai][7] + bv1.w);
                float* op = out + (size_t)mg * E + n0;
                *reinterpret_cast<float4*>(op + col0)      = o0;
                *reinterpret_cast<float4*>(op + col0 + 64) = o1;
            }
        }
    }
}

} // namespace

extern "C" void kernel_launch(void* const* d_in, const int* in_sizes, int n_in,
                              void* d_out, int out_size) {
    const float* x     = (const float*)d_in[0];  // [96, 4, 420, 312]
    const float* Wm    = (const float*)d_in[1];  // [768, 672]
    const float* b     = (const float*)d_in[2];  // [768]
    const int*   valid = (const int*)  d_in[3];  // [390]
    float*       out   = (float*)d_out;          // [37440, 768]

    dim3 grid((M + BM - 1) / BM, E / BN);        // (293, 6)
    patch_embed_gemm<<<grid, 256>>>(x, Wm, b, valid, out);
}

// round 6
// speedup vs baseline: 2.5439x; 2.5439x over previous
#include <cuda_runtime.h>
#include <cstdint>

// PatchEmbedding as implicit-im2col TF32 GEMM using sm_80-baseline
// mma.sync.m16n8k8.tf32 + ldmatrix (no sm_103a-gated instructions).
//   D[M=37440, N=768] = A[M,672] * B^T,  B = Wm [768,672] (K-major, native)
//   A gathered from x; + bias; both operands rounded via cvt.rna.tf32.

namespace {

constexpr int C_   = 4;
constexpr int Himg = 420;
constexpr int Wimg = 312;
constexpr int PH   = 14;
constexpr int PW   = 12;
constexpr int GW   = 26;
constexpr int E    = 768;
constexpr int NV   = 390;
constexpr int K    = 672;
constexpr int M    = 96 * NV;        // 37440
constexpr int HW_  = Himg * Wimg;    // 131040
constexpr int CHW  = C_ * HW_;

constexpr int BM = 128, BN = 128, BK = 32;
constexpr int NKT  = K / BK;             // 21
constexpr int NBLK = E / BN;             // 6
constexpr int MBLK = (M + BM - 1) / BM;  // 293

// dynamic SMEM layout
constexpr int SM_ROWBASE = 0;                       // 128 ints
constexpr int SM_A0 = 1024;                         // 128 x 128B = 16KB
constexpr int SM_A1 = SM_A0 + BM * BK * 4;
constexpr int SM_B0 = SM_A1 + BM * BK * 4;          // 128 x 128B
constexpr int SM_B1 = SM_B0 + BN * BK * 4;
constexpr int SM_TOTAL = SM_B1 + BN * BK * 4;       // 66560

__device__ __forceinline__ uint32_t smem_u32(const void* p) {
    uint32_t a;
    asm("{ .reg .u64 t; cvta.to.shared.u64 t, %1; cvt.u32.u64 %0, t; }"
        : "=r"(a) : "l"(p));
    return a;
}

__device__ __forceinline__ uint32_t f2tf32(float v) {
    uint32_t r;
    asm("cvt.rna.tf32.f32 %0, %1;" : "=r"(r) : "f"(v));
    return r;
}

__device__ __forceinline__ uint32_t swz(uint32_t off) {
    return off ^ ((off >> 3) & 0x70);   // SW128: XOR bits[9:7] into [6:4]
}

__device__ __forceinline__ void ldsm_x4(uint32_t r[4], uint32_t addr) {
    asm volatile("ldmatrix.sync.aligned.m8n8.x4.shared.b16 {%0,%1,%2,%3}, [%4];"
                 : "=r"(r[0]), "=r"(r[1]), "=r"(r[2]), "=r"(r[3]) : "r"(addr));
}

__device__ __forceinline__ void mma_tf32(float d[4], const uint32_t a[4],
                                         uint32_t b0, uint32_t b1) {
    asm volatile(
        "mma.sync.aligned.m16n8k8.row.col.f32.tf32.tf32.f32 "
        "{%0,%1,%2,%3}, {%4,%5,%6,%7}, {%8,%9}, {%0,%1,%2,%3};"
        : "+f"(d[0]), "+f"(d[1]), "+f"(d[2]), "+f"(d[3])
        : "r"(a[0]), "r"(a[1]), "r"(a[2]), "r"(a[3]), "r"(b0), "r"(b1));
}

__global__ __launch_bounds__(256)
void patch_embed_mma(const float* __restrict__ x,
                     const float* __restrict__ Wm,
                     const float* __restrict__ bias,
                     const int*   __restrict__ valid,
                     float*       __restrict__ out)
{
    extern __shared__ char smem[];
    const uint32_t sb = smem_u32(smem);
    int* rowbase = reinterpret_cast<int*>(smem + SM_ROWBASE);

    const int tid  = threadIdx.x;
    const int lane = tid & 31;
    const int wid  = tid >> 5;

    // n-blocks innermost in bid order -> 6 N-passes over same A-panel hit L2
    const int bid  = blockIdx.x;
    const int n0   = (bid % NBLK) * BN;
    const int m0   = (bid / NBLK) * BM;

    // per-row patch base offsets
    if (tid < BM) {
        int mg = m0 + tid;
        int base = -1;
        if (mg < M) {
            int n  = mg / NV;
            int v  = mg - n * NV;
            int p  = valid[v];
            int gi = p / GW;
            int gj = p - gi * GW;
            base = n * CHW + gi * (PH * Wimg) + gj * PW;
        }
        rowbase[tid] = base;
    }
    __syncthreads();

    // ---- global-load assignments ----
    const int kc   = lane;        // A: k within tile (warp = 32 consecutive k)
    const int wrow = wid;         // A: rows p*8 + wid, p=0..15
    const int brow = tid >> 3;    // B: rows p*32 + brow, p=0..3
    const int bf   = tid & 7;     // B: float4 within 32-k row

    // ---- fragment (warp-tile) assignments: 2(M) x 4(N) warps ----
    const int wm = (wid & 1) * 64;
    const int wn = (wid >> 1) * 32;
    const int arow_l = lane & 15;                         // A ldmatrix row
    const int aq_l   = lane >> 4;                         // A ldmatrix quad sel
    const int brow_l = (lane & 7) + ((lane >> 4) << 3);   // B ldmatrix row
    const int bq_l   = (lane >> 3) & 1;                   // B ldmatrix quad sel

    float d[4][4][4];
    #pragma unroll
    for (int i = 0; i < 4; ++i)
        #pragma unroll
        for (int j = 0; j < 4; ++j)
            #pragma unroll
            for (int r = 0; r < 4; ++r)
                d[i][j][r] = 0.0f;

    float  ar[16];
    float4 br[4];

    // ---- prologue: stage tile 0 ----
    {
        int k   = kc;
        int c   = k / (PH * PW);
        int rem = k - c * (PH * PW);
        int r   = rem / PW;
        int q   = rem - r * PW;
        int ko  = c * HW_ + r * Wimg + q;
        #pragma unroll
        for (int p = 0; p < 16; ++p) {
            int rb = rowbase[p * 8 + wrow];
            ar[p] = (rb >= 0) ? __ldg(x + rb + ko) : 0.0f;
        }
        #pragma unroll
        for (int p = 0; p < 4; ++p)
            br[p] = __ldg(reinterpret_cast<const float4*>(
                Wm + (size_t)(n0 + p * 32 + brow) * K + bf * 4));
    }

    for (int kt = 0; kt < NKT; ++kt) {
        const uint32_t abase = sb + ((kt & 1) ? SM_A1 : SM_A0);
        const uint32_t bbase = sb + ((kt & 1) ? SM_B1 : SM_B0);

        // staged regs -> smem (rounded to tf32, swizzled)
        #pragma unroll
        for (int p = 0; p < 16; ++p) {
            uint32_t off = swz((p * 8 + wrow) * 128 + kc * 4);
            uint32_t u   = f2tf32(ar[p]);
            asm volatile("st.shared.b32 [%0], %1;" :: "r"(abase + off), "r"(u)
                         : "memory");
        }
        #pragma unroll
        for (int p = 0; p < 4; ++p) {
            uint32_t off = swz((p * 32 + brow) * 128 + bf * 16);
            uint32_t u0 = f2tf32(br[p].x), u1 = f2tf32(br[p].y);
            uint32_t u2 = f2tf32(br[p].z), u3 = f2tf32(br[p].w);
            asm volatile("st.shared.v4.b32 [%0], {%1,%2,%3,%4};"
                         :: "r"(bbase + off), "r"(u0), "r"(u1), "r"(u2), "r"(u3)
                         : "memory");
        }
        __syncthreads();

        // prefetch next tile while computing this one
        if (kt + 1 < NKT) {
            int k   = (kt + 1) * BK + kc;
            int c   = k / (PH * PW);
            int rem = k - c * (PH * PW);
            int r   = rem / PW;
            int q   = rem - r * PW;
            int ko  = c * HW_ + r * Wimg + q;
            #pragma unroll
            for (int p = 0; p < 16; ++p) {
                int rb = rowbase[p * 8 + wrow];
                ar[p] = (rb >= 0) ? __ldg(x + rb + ko) : 0.0f;
            }
            #pragma unroll
            for (int p = 0; p < 4; ++p)
                br[p] = __ldg(reinterpret_cast<const float4*>(
                    Wm + (size_t)(n0 + p * 32 + brow) * K + (kt + 1) * BK + bf * 4));
        }

        // ---- tensor compute: 4 k8 steps ----
        #pragma unroll
        for (int s = 0; s < 4; ++s) {
            uint32_t a[4][4];
            uint32_t b[2][4];
            #pragma unroll
            for (int i = 0; i < 4; ++i) {
                uint32_t off = swz((wm + i * 16 + arow_l) * 128 +
                                   (2 * s + aq_l) * 16);
                ldsm_x4(a[i], abase + off);
            }
            #pragma unroll
            for (int t = 0; t < 2; ++t) {
                uint32_t off = swz((wn + t * 16 + brow_l) * 128 +
                                   (2 * s + bq_l) * 16);
                ldsm_x4(b[t], bbase + off);
            }
            #pragma unroll
            for (int i = 0; i < 4; ++i)
                #pragma unroll
                for (int j = 0; j < 4; ++j)
                    mma_tf32(d[i][j], a[i],
                             b[j >> 1][(j & 1) * 2], b[j >> 1][(j & 1) * 2 + 1]);
        }
        __syncthreads();
    }

    // ---- epilogue: + bias, direct float2 stores (32B sectors, fully written)
    const int g  = lane >> 2;
    const int c2 = (lane & 3) * 2;
    #pragma unroll
    for (int j = 0; j < 4; ++j) {
        const int col = n0 + wn + j * 8 + c2;
        const float2 bv = *reinterpret_cast<const float2*>(bias + col);
        #pragma unroll
        for (int i = 0; i < 4; ++i) {
            int r0 = m0 + wm + i * 16 + g;
            if (r0 < M) {
                float2 o = make_float2(d[i][j][0] + bv.x, d[i][j][1] + bv.y);
                *reinterpret_cast<float2*>(out + (size_t)r0 * E + col) = o;
            }
            int r1 = r0 + 8;
            if (r1 < M) {
                float2 o = make_float2(d[i][j][2] + bv.x, d[i][j][3] + bv.y);
                *reinterpret_cast<float2*>(out + (size_t)r1 * E + col) = o;
            }
        }
    }
}

} // namespace

extern "C" void kernel_launch(void* const* d_in, const int* in_sizes, int n_in,
                              void* d_out, int out_size) {
    const float* x     = (const float*)d_in[0];  // [96, 4, 420, 312]
    const float* Wm    = (const float*)d_in[1];  // [768, 672]
    const float* b     = (const float*)d_in[2];  // [768]
    const int*   valid = (const int*)  d_in[3];  // [390]
    float*       out   = (float*)d_out;          // [37440, 768]

    cudaFuncSetAttribute(patch_embed_mma,
                         cudaFuncAttributeMaxDynamicSharedMemorySize, SM_TOTAL);
    patch_embed_mma<<<MBLK * NBLK, 256, SM_TOTAL>>>(x, Wm, b, valid, out);
}

// round 7
// speedup vs baseline: 2.5867x; 1.0168x over previous
#include <cuda_runtime.h>
#include <cstdint>

// PatchEmbedding, 3-kernel plan:
//   1) round_w:  W [768,672] -> tf32-rounded copy Wr (2 MB)
//   2) im2col:   x gather -> tf32-rounded A matrix Ar [37440,672] (100 MB)
//   3) gemm:     D = Ar * Wr^T + bias  via cp.async-pipelined mma.m16n8k8.tf32

namespace {

constexpr int C_   = 4;
constexpr int Himg = 420;
constexpr int Wimg = 312;
constexpr int PH   = 14;
constexpr int PW   = 12;
constexpr int GW   = 26;
constexpr int E    = 768;
constexpr int NV   = 390;
constexpr int K    = 672;
constexpr int M    = 96 * NV;        // 37440
constexpr int HW_  = Himg * Wimg;
constexpr int CHW  = C_ * HW_;

constexpr int BM = 128, BN = 128, BK = 32;
constexpr int NKT    = K / BK;             // 21
constexpr int NBLK   = E / BN;             // 6
constexpr int MBLK   = (M + BM - 1) / BM;  // 293
constexpr int STAGES = 3;
constexpr int STAGE_BYTES = (BM + BN) * BK * 4;       // 32 KB
constexpr int SM_TOTAL    = STAGES * STAGE_BYTES;      // 96 KB

} // namespace

// scratch (module-scope device globals; allocation-free at launch time)
__device__ float g_Ar[(size_t)M * K];   // ~100.6 MB, im2col'd + tf32-rounded
__device__ float g_Wr[(size_t)E * K];   // ~2 MB, tf32-rounded

namespace {

__device__ __forceinline__ uint32_t smem_u32(const void* p) {
    uint32_t a;
    asm("{ .reg .u64 t; cvta.to.shared.u64 t, %1; cvt.u32.u64 %0, t; }"
        : "=r"(a) : "l"(p));
    return a;
}

__device__ __forceinline__ uint32_t f2tf32(float v) {
    uint32_t r;
    asm("cvt.rna.tf32.f32 %0, %1;" : "=r"(r) : "f"(v));
    return r;
}

__device__ __forceinline__ void cp16(uint32_t dst, const float* src) {
    asm volatile("cp.async.cg.shared.global [%0], [%1], 16;"
                 :: "r"(dst), "l"(src) : "memory");
}

__device__ __forceinline__ void ldsm_x4(uint32_t r[4], uint32_t addr) {
    asm volatile("ldmatrix.sync.aligned.m8n8.x4.shared.b16 {%0,%1,%2,%3}, [%4];"
                 : "=r"(r[0]), "=r"(r[1]), "=r"(r[2]), "=r"(r[3]) : "r"(addr));
}

__device__ __forceinline__ void mma_tf32(float d[4], const uint32_t a[4],
                                         uint32_t b0, uint32_t b1) {
    asm volatile(
        "mma.sync.aligned.m16n8k8.row.col.f32.tf32.tf32.f32 "
        "{%0,%1,%2,%3}, {%4,%5,%6,%7}, {%8,%9}, {%0,%1,%2,%3};"
        : "+f"(d[0]), "+f"(d[1]), "+f"(d[2]), "+f"(d[3])
        : "r"(a[0]), "r"(a[1]), "r"(a[2]), "r"(a[3]), "r"(b0), "r"(b1));
}

// ---- pre-pass 1: round W to tf32 ----
__global__ void round_w(const float* __restrict__ Wm) {
    int i = blockIdx.x * blockDim.x + threadIdx.x;   // float4 index
    constexpr int N4 = E * K / 4;
    if (i < N4) {
        float4 v = reinterpret_cast<const float4*>(Wm)[i];
        v.x = __uint_as_float(f2tf32(v.x));
        v.y = __uint_as_float(f2tf32(v.y));
        v.z = __uint_as_float(f2tf32(v.z));
        v.w = __uint_as_float(f2tf32(v.w));
        reinterpret_cast<float4*>(g_Wr)[i] = v;
    }
}

// ---- pre-pass 2: im2col gather + tf32 round. one block per output row ----
__global__ __launch_bounds__(256)
void im2col(const float* __restrict__ x, const int* __restrict__ valid) {
    const int m = blockIdx.x;
    const int n = m / NV;
    const int v = m - n * NV;
    const int p = valid[v];
    const int gi = p / GW;
    const int gj = p - gi * GW;
    const int base = n * CHW + gi * (PH * Wimg) + gj * PW;

    for (int k = threadIdx.x; k < K; k += 256) {
        int c   = k / (PH * PW);
        int rem = k - c * (PH * PW);
        int r   = rem / PW;
        int q   = rem - r * PW;
        float val = __ldg(x + base + c * HW_ + r * Wimg + q);
        g_Ar[(size_t)m * K + k] = __uint_as_float(f2tf32(val));
    }
}

// ---- main GEMM: cp.async 3-stage pipeline + mma.m16n8k8.tf32 ----
__global__ __launch_bounds__(256, 2)
void patch_embed_gemm(const float* __restrict__ bias,
                      float*       __restrict__ out)
{
    extern __shared__ char smem[];
    const uint32_t sb = smem_u32(smem);

    const int tid  = threadIdx.x;
    const int lane = tid & 31;
    const int wid  = tid >> 5;

    const int bid = blockIdx.x;
    const int n0  = (bid % NBLK) * BN;   // n innermost -> A panel L2 reuse
    const int m0  = (bid / NBLK) * BM;

    // ---- cp.async assignment: thread -> (row, 4 x 16B chunks) ----
    const int      row    = tid >> 1;                   // 0..127
    const int      cbase  = (tid & 1) * 64;             // byte col base (0 or 64)
    const uint32_t row128 = row * 128;
    const uint32_t xm     = (row << 4) & 0x70;          // per-row swizzle mask
    const int      arow   = (m0 + row < M) ? (m0 + row) : (M - 1);  // clamp
    const float*   asrc0  = g_Ar + (size_t)arow * K + (tid & 1) * 16;
    const float*   bsrc0  = g_Wr + (size_t)(n0 + row) * K + (tid & 1) * 16;

    auto issue = [&](int kt) {
        const uint32_t ab = sb + (kt % STAGES) * STAGE_BYTES;
        const uint32_t bb = ab + BM * BK * 4;
        const float* as = asrc0 + kt * BK;
        const float* bs = bsrc0 + kt * BK;
        #pragma unroll
        for (int j = 0; j < 4; ++j) {
            uint32_t off = row128 + ((cbase + j * 16) ^ xm);
            cp16(ab + off, as + j * 4);
            cp16(bb + off, bs + j * 4);
        }
    };

    // ---- fragment assignment: 2(M) x 4(N) warps, warp tile 64x32 ----
    const int wm = (wid & 1) * 64;
    const int wn = (wid >> 1) * 32;
    const int arow_l = lane & 15;
    const int aq_l   = lane >> 4;
    const int brow_l = (lane & 7) + ((lane >> 4) << 3);
    const int bq_l   = (lane >> 3) & 1;

    float d[4][4][4];
    #pragma unroll
    for (int i = 0; i < 4; ++i)
        #pragma unroll
        for (int j = 0; j < 4; ++j)
            #pragma unroll
            for (int r = 0; r < 4; ++r)
                d[i][j][r] = 0.0f;

    // prologue: stages 0, 1 in flight
    issue(0);
    asm volatile("cp.async.commit_group;" ::: "memory");
    issue(1);
    asm volatile("cp.async.commit_group;" ::: "memory");

    for (int kt = 0; kt < NKT; ++kt) {
        asm volatile("cp.async.wait_group 1;" ::: "memory");
        __syncthreads();                  // stage kt visible; buf (kt+2)%3 free

        if (kt + 2 < NKT) issue(kt + 2);
        asm volatile("cp.async.commit_group;" ::: "memory");

        const uint32_t abase = sb + (kt % STAGES) * STAGE_BYTES;
        const uint32_t bbase = abase + BM * BK * 4;

        #pragma unroll
        for (int s = 0; s < 4; ++s) {
            uint32_t a[4][4];
            uint32_t b[2][4];
            #pragma unroll
            for (int i = 0; i < 4; ++i) {
                int r = wm + i * 16 + arow_l;
                uint32_t off = r * 128 + (((2 * s + aq_l) * 16) ^ ((r << 4) & 0x70));
                ldsm_x4(a[i], abase + off);
            }
            #pragma unroll
            for (int t = 0; t < 2; ++t) {
                int r = wn + t * 16 + brow_l;
                uint32_t off = r * 128 + (((2 * s + bq_l) * 16) ^ ((r << 4) & 0x70));
                ldsm_x4(b[t], bbase + off);
            }
            #pragma unroll
            for (int i = 0; i < 4; ++i)
                #pragma unroll
                for (int j = 0; j < 4; ++j)
                    mma_tf32(d[i][j], a[i],
                             b[j >> 1][(j & 1) * 2], b[j >> 1][(j & 1) * 2 + 1]);
        }
    }

    // ---- epilogue: + bias, direct float2 stores ----
    const int g  = lane >> 2;
    const int c2 = (lane & 3) * 2;
    #pragma unroll
    for (int j = 0; j < 4; ++j) {
        const int col = n0 + wn + j * 8 + c2;
        const float2 bv = *reinterpret_cast<const float2*>(bias + col);
        #pragma unroll
        for (int i = 0; i < 4; ++i) {
            int r0 = m0 + wm + i * 16 + g;
            if (r0 < M) {
                float2 o = make_float2(d[i][j][0] + bv.x, d[i][j][1] + bv.y);
                *reinterpret_cast<float2*>(out + (size_t)r0 * E + col) = o;
            }
            int r1 = r0 + 8;
            if (r1 < M) {
                float2 o = make_float2(d[i][j][2] + bv.x, d[i][j][3] + bv.y);
                *reinterpret_cast<float2*>(out + (size_t)r1 * E + col) = o;
            }
        }
    }
}

} // namespace

extern "C" void kernel_launch(void* const* d_in, const int* in_sizes, int n_in,
                              void* d_out, int out_size) {
    const float* x     = (const float*)d_in[0];  // [96, 4, 420, 312]
    const float* Wm    = (const float*)d_in[1];  // [768, 672]
    const float* b     = (const float*)d_in[2];  // [768]
    const int*   valid = (const int*)  d_in[3];  // [390]
    float*       out   = (float*)d_out;          // [37440, 768]

    round_w<<<(E * K / 4 + 255) / 256, 256>>>(Wm);
    im2col<<<M, 256>>>(x, valid);

    cudaFuncSetAttribute(patch_embed_gemm,
                         cudaFuncAttributeMaxDynamicSharedMemorySize, SM_TOTAL);
    patch_embed_gemm<<<MBLK * NBLK, 256, SM_TOTAL>>>(b, out);
}